// round 6
// baseline (speedup 1.0000x reference)
#include <cuda_runtime.h>

// ---------------------------------------------------------------------------
// Seq2seq LSTM, ONE persistent kernel, GRID=128 CTAs (1/SM), software barrier.
// Round 6: 512 threads (16 warps, occ 25%), 32 j-tiles x 4 row groups,
// resident W = 3x32KB/CTA, 3-stage 32KB cp.async ring with ONE sync per chunk,
// all LDS fragment loads 1 wavefront. Gate-spread register-only epilogues,
// fused projection (shfl + atomicAdd), skewed encoder.
// ---------------------------------------------------------------------------

#define HID   256
#define BATCH 256
#define TLEN  512
#define NS    16
#define SBAT  4096
#define HOR   64
#define GRID  128
#define NTHR  512

#define WREG     32768
#define A_OFF    (3 * WREG)          // 98304
#define A_STAGE  32768
#define SMEM_BYTES (A_OFF + 3 * A_STAGE)   // 196608 (192KB)

// ---------------- device state ----------------------------------------------
__device__ float g_eh0[2][BATCH * HID];
__device__ float g_ec0[BATCH * HID];
__device__ float g_eh1[2][BATCH * HID];
__device__ float g_ec1[BATCH * HID];

__device__ float g_dh0[2][SBAT * HID];
__device__ float g_dc0[SBAT * HID];
__device__ float g_dh1[2][SBAT * HID];
__device__ float g_dc1[SBAT * HID];
__device__ float g_pred[2][SBAT];

__device__ unsigned g_cnt = 0;
__device__ volatile unsigned g_gen = 0;

// ---------------- grid-wide barrier ------------------------------------------
__device__ __forceinline__ void gsync() {
    __syncthreads();
    if (threadIdx.x == 0) {
        __threadfence();
        unsigned old = g_gen;
        unsigned arrived = atomicAdd(&g_cnt, 1u);
        if (arrived == gridDim.x - 1) {
            g_cnt = 0;
            __threadfence();
            g_gen = old + 1u;
        } else {
            while (g_gen == old) { }
            __threadfence();
        }
    }
    __syncthreads();
}

// ---------------- packed f32x2 FMA -------------------------------------------
union F2U { float2 f; unsigned long long u; };

__device__ __forceinline__ float2 ffma2(float2 a, float2 b, float2 c) {
    F2U ua, ub, uc;
    ua.f = a; ub.f = b; uc.f = c;
    asm("fma.rn.f32x2 %0, %1, %2, %0;" : "+l"(uc.u) : "l"(ua.u), "l"(ub.u));
    return uc.f;
}

__device__ __forceinline__ float sigm(float x) {
    return 1.0f / (1.0f + expf(-x));
}

// ---------------- cp.async helpers -------------------------------------------
__device__ __forceinline__ void cpa16(void* dst, const void* src) {
    unsigned d = (unsigned)__cvta_generic_to_shared(dst);
    asm volatile("cp.async.cg.shared.global [%0], [%1], 16;" :: "r"(d), "l"(src));
}
__device__ __forceinline__ void cp_commit() {
    asm volatile("cp.async.commit_group;" ::: "memory");
}
__device__ __forceinline__ void cp_wait0() {
    asm volatile("cp.async.wait_group 0;" ::: "memory");
}
__device__ __forceinline__ void cp_wait1() {
    asm volatile("cp.async.wait_group 1;" ::: "memory");
}

// ---------------------------------------------------------------------------
// Resident W region (32KB): Wf[k4*32 + gate*8 + jj], jj = local j (8 per CTA).
// ---------------------------------------------------------------------------
__device__ __forceinline__ void load_W_region(char* dst, const float* __restrict__ W,
                                              int j0, int tid) {
    float4* Wf = (float4*)dst;
#pragma unroll
    for (int i = tid; i < 2048; i += NTHR) {
        int k4 = i & 63, s = i >> 6;
        int gate = s >> 3, jj = s & 7;
        cpa16(&Wf[k4 * 32 + s], W + (size_t)(gate * HID + j0 + jj) * HID + k4 * 4);
    }
}

// A chunk loaders (32KB stages). Af[q*TB + r] = A[r][kc+4q .. kc+4q+3].
__device__ __forceinline__ void issue_Ae(char* stage, const float* __restrict__ A,
                                         int kc, int tid) {  // 64 rows x K128
    float4* Af = (float4*)stage;
#pragma unroll
    for (int i = tid; i < 2048; i += NTHR) {
        int r = i >> 5, q = i & 31;
        cpa16(&Af[q * 64 + r], A + (size_t)r * HID + kc + q * 4);
    }
}
__device__ __forceinline__ void issue_Ad(char* stage, const float* __restrict__ A,
                                         int kc, int tid) {  // 128 rows x K64
    float4* Af = (float4*)stage;
#pragma unroll
    for (int i = tid; i < 2048; i += NTHR) {
        int r = i >> 4, q = i & 15;
        cpa16(&Af[q * 128 + r], A + (size_t)r * HID + kc + q * 4);
    }
}

// ---------------------------------------------------------------------------
// GEMM over one chunk. Thread (ty = tid>>3, tx = tid&7):
//   rows ty + 64r (r < RB), cols j0+tx across 4 gates.
//   a4[r] = Af[k4*TB + ty + 64r]   (8 distinct/warp -> 1 wavefront)
//   b4[c] = Wfc[k4*32 + c*8 + tx]  (8 distinct/warp -> 1 wavefront)
// ---------------------------------------------------------------------------
template<int TB, int RB, int NK4>
__device__ __forceinline__ void gemm_chunk(const char* stage,
                                           const float4* __restrict__ Wfc,
                                           float2 (&acc)[RB][4],
                                           int ty, int tx)
{
    const float4* __restrict__ Af = (const float4*)stage;
#pragma unroll 2
    for (int k4 = 0; k4 < NK4; ++k4) {
        const float4* bp = Wfc + k4 * 32 + tx;
        float4 b4[4];
#pragma unroll
        for (int c = 0; c < 4; ++c) b4[c] = bp[c * 8];
        const float4* ap = Af + k4 * TB + ty;
        float4 a4[RB];
#pragma unroll
        for (int r = 0; r < RB; ++r) a4[r] = ap[r * 64];
#pragma unroll
        for (int r = 0; r < RB; ++r)
#pragma unroll
            for (int c = 0; c < 4; ++c) {
                acc[r][c] = ffma2(make_float2(a4[r].x, a4[r].y),
                                  make_float2(b4[c].x, b4[c].y), acc[r][c]);
                acc[r][c] = ffma2(make_float2(a4[r].z, a4[r].w),
                                  make_float2(b4[c].z, b4[c].w), acc[r][c]);
            }
    }
}

// ---------------------------------------------------------------------------
__global__ void __launch_bounds__(NTHR, 1)
lstm_all(const float* __restrict__ x,
         const float* __restrict__ eWih0, const float* __restrict__ eWhh0,
         const float* __restrict__ eb0,
         const float* __restrict__ eWih1, const float* __restrict__ eWhh1,
         const float* __restrict__ eb1,
         const float* __restrict__ dWih0, const float* __restrict__ dWhh0,
         const float* __restrict__ db0,
         const float* __restrict__ dWih1, const float* __restrict__ dWhh1,
         const float* __restrict__ db1,
         const float* __restrict__ outW, const float* __restrict__ outb,
         const float* __restrict__ dinit,
         float* __restrict__ out)
{
    extern __shared__ char smem[];
    const int tid = threadIdx.x;
    const int ty = tid >> 3, tx = tid & 7;      // 64 x 8
    const int jt  = blockIdx.x >> 2;            // 0..31
    const int j0  = jt * 8;
    const int grp = blockIdx.x & 3;             // row group
    const int eRow0 = grp * 64;                 // encoder: 64 rows
    const int dRow0 = grp * 1024;               // decoder: 1024 rows (8 tiles)

    const float4* W0f = (const float4*)(smem);
    const float4* W1f = (const float4*)(smem + WREG);
    const float4* W2f = (const float4*)(smem + 2 * WREG);
    char* stg[3] = { smem + A_OFF, smem + A_OFF + A_STAGE, smem + A_OFF + 2 * A_STAGE };

    // ---- per-thread constants (fixed j column) ----
    float e_bv0[4], e_wv0[4], e_bv1[4];
#pragma unroll
    for (int c = 0; c < 4; ++c) {
        int gr = c * HID + j0 + tx;
        e_bv0[c] = eb0[gr];
        e_wv0[c] = eWih0[gr];
        e_bv1[c] = eb1[gr];
    }

    // ---- resident encoder weights + zero-init state ----
    load_W_region(smem,            eWhh0, j0, tid);
    load_W_region(smem + WREG,     eWih1, j0, tid);
    load_W_region(smem + 2 * WREG, eWhh1, j0, tid);
    cp_commit();
    for (int i = blockIdx.x * NTHR + tid; i < BATCH * HID; i += GRID * NTHR) {
        g_eh0[1][i] = 0.f; g_ec0[i] = 0.f;
        g_eh1[1][i] = 0.f; g_ec1[i] = 0.f;
    }
    cp_wait0();
    gsync();

    // =========================== encoder (skewed) ===========================
    // phase p: layer0(t=p) if p<TLEN, layer1(t'=p-1) if p>0.
    // chunks: [0,n0): L0 on h0(p-1); [n0,n): L1 (2x Wih1 on h0(p-1), 2x Whh1
    // on h1(p-2)). All chunks are 64 rows x K=128.
    for (int p = 0; p <= TLEN; ++p) {
        const float* hA  = g_eh0[(p + 1) & 1] + (size_t)eRow0 * HID;
        const float* h1r = g_eh1[p & 1]       + (size_t)eRow0 * HID;
        const int n0 = (p < TLEN) ? 2 : 0;
        const int n  = n0 + ((p > 0) ? 4 : 0);

        // chunk i classification
        auto cA  = [&](int i) -> const float* {
            if (i < n0) return hA;
            return ((i - n0) < 2) ? hA : h1r;
        };
        auto cKC = [&](int i) -> int {
            int j = (i < n0) ? i : (i - n0);
            return (j & 1) * 128;
        };

        float2 acc0[1][4], acc1[1][4];
#pragma unroll
        for (int c = 0; c < 4; ++c) {
            acc0[0][c] = make_float2(0.f, 0.f);
            acc1[0][c] = make_float2(0.f, 0.f);
        }

        issue_Ae(stg[0], cA(0), cKC(0), tid); cp_commit();
        issue_Ae(stg[1], cA(1), cKC(1), tid); cp_commit();

        for (int i = 0; i < n; ++i) {
            if (i + 1 < n) cp_wait1(); else cp_wait0();
            __syncthreads();
            if (i + 2 < n) {
                issue_Ae(stg[(i + 2) % 3], cA(i + 2), cKC(i + 2), tid);
                cp_commit();
            }
            if (i < n0) {
                gemm_chunk<64, 1, 32>(stg[i % 3], W0f + (i & 1) * 32 * 32, acc0, ty, tx);
            } else {
                int j = i - n0;
                const float4* wr = (j < 2) ? W1f : W2f;
                gemm_chunk<64, 1, 32>(stg[i % 3], wr + (j & 1) * 32 * 32, acc1, ty, tx);
            }

            if (p < TLEN && i == n0 - 1) {
                // layer0 epilogue, t = p
                int row = eRow0 + ty;
                float xv = x[(size_t)row * TLEN + p];
                float gi = acc0[0][0].x + acc0[0][0].y + e_bv0[0] + xv * e_wv0[0];
                float gf = acc0[0][1].x + acc0[0][1].y + e_bv0[1] + xv * e_wv0[1];
                float gg = acc0[0][2].x + acc0[0][2].y + e_bv0[2] + xv * e_wv0[2];
                float go = acc0[0][3].x + acc0[0][3].y + e_bv0[3] + xv * e_wv0[3];
                int idx = row * HID + j0 + tx;
                float cn = sigm(gf) * g_ec0[idx] + sigm(gi) * tanhf(gg);
                g_ec0[idx] = cn;
                g_eh0[p & 1][idx] = sigm(go) * tanhf(cn);
            }
            if (p > 0 && i == n - 1) {
                // layer1 epilogue, t' = p-1
                int row = eRow0 + ty;
                float gi = acc1[0][0].x + acc1[0][0].y + e_bv1[0];
                float gf = acc1[0][1].x + acc1[0][1].y + e_bv1[1];
                float gg = acc1[0][2].x + acc1[0][2].y + e_bv1[2];
                float go = acc1[0][3].x + acc1[0][3].y + e_bv1[3];
                int idx = row * HID + j0 + tx;
                float cn = sigm(gf) * g_ec1[idx] + sigm(gi) * tanhf(gg);
                g_ec1[idx] = cn;
                g_eh1[(p + 1) & 1][idx] = sigm(go) * tanhf(cn);
            }
        }
        gsync();
    }

    // ============== decoder setup: W reload + state broadcast ================
    load_W_region(smem,            dWhh0, j0, tid);
    load_W_region(smem + WREG,     dWih1, j0, tid);
    load_W_region(smem + 2 * WREG, dWhh1, j0, tid);
    cp_commit();
    for (int i = blockIdx.x * NTHR + tid; i < SBAT * HID; i += GRID * NTHR) {
        int src = i & (BATCH * HID - 1);
        g_dh0[1][i] = g_eh0[1][src];
        g_dc0[i]    = g_ec0[src];
        g_dh1[1][i] = g_eh1[1][src];
        g_dc1[i]    = g_ec1[src];
    }
    cp_wait0();
    gsync();

    float d_bv0[4], d_wv0[4], d_bv1[4];
#pragma unroll
    for (int c = 0; c < 4; ++c) {
        int gr = c * HID + j0 + tx;
        d_bv0[c] = db0[gr];
        d_wv0[c] = dWih0[gr];
        d_bv1[c] = db1[gr];
    }
    const float outw  = outW[j0 + tx];
    const float outbv = outb[0];

    // =========================== decoder =====================================
    // Per CTA per phase: 8 row tiles of 128; chunks are 128 rows x K=64.
    for (int t = 0; t < HOR; ++t) {
        const int rp = (t + 1) & 1, wp = t & 1;

        // ---- layer0: 8 tiles x 4 chunks = 32 chunks ----
        if (tid < 32) g_pred[wp][blockIdx.x * 32 + tid] = 0.f;
        {
            const float* h0r = g_dh0[rp];
            float2 acc[2][4];
            issue_Ad(stg[0], h0r + (size_t)dRow0 * HID, 0,  tid); cp_commit();
            issue_Ad(stg[1], h0r + (size_t)dRow0 * HID, 64, tid); cp_commit();
            for (int i = 0; i < 32; ++i) {
                if ((i & 3) == 0) {
#pragma unroll
                    for (int r = 0; r < 2; ++r)
#pragma unroll
                        for (int c = 0; c < 4; ++c) acc[r][c] = make_float2(0.f, 0.f);
                }
                if (i + 1 < 32) cp_wait1(); else cp_wait0();
                __syncthreads();
                if (i + 2 < 32) {
                    int ni = i + 2;
                    issue_Ad(stg[ni % 3],
                             h0r + (size_t)(dRow0 + (ni >> 2) * 128) * HID,
                             (ni & 3) * 64, tid);
                    cp_commit();
                }
                gemm_chunk<128, 2, 16>(stg[i % 3], W0f + (i & 3) * 16 * 32, acc, ty, tx);

                if ((i & 3) == 3) {
                    int base = dRow0 + (i >> 2) * 128;
#pragma unroll
                    for (int r = 0; r < 2; ++r) {
                        int row = base + ty + 64 * r;
                        float iv;
                        if (t == 0) {
                            iv = dinit[row];
                        } else {
                            iv = __ldcg(&g_pred[rp][row]) + outbv;
                            if (jt == 0 && tx == 0)
                                out[(size_t)(row & 255) * (NS * HOR)
                                    + (row >> 8) * HOR + (t - 1)] = iv;
                        }
                        float gi = acc[r][0].x + acc[r][0].y + d_bv0[0] + iv * d_wv0[0];
                        float gf = acc[r][1].x + acc[r][1].y + d_bv0[1] + iv * d_wv0[1];
                        float gg = acc[r][2].x + acc[r][2].y + d_bv0[2] + iv * d_wv0[2];
                        float go = acc[r][3].x + acc[r][3].y + d_bv0[3] + iv * d_wv0[3];
                        int idx = row * HID + j0 + tx;
                        float cn = sigm(gf) * g_dc0[idx] + sigm(gi) * tanhf(gg);
                        g_dc0[idx] = cn;
                        g_dh0[wp][idx] = sigm(go) * tanhf(cn);
                    }
                }
            }
        }
        gsync();

        // ---- layer1: 8 tiles x 8 chunks (4x Wih1 on h0cur, 4x Whh1 on h1prev) ----
        {
            const float* h0c = g_dh0[wp];
            const float* h1r = g_dh1[rp];
            float2 acc[2][4];
            issue_Ad(stg[0], h0c + (size_t)dRow0 * HID, 0,  tid); cp_commit();
            issue_Ad(stg[1], h0c + (size_t)dRow0 * HID, 64, tid); cp_commit();
            for (int i = 0; i < 64; ++i) {
                if ((i & 7) == 0) {
#pragma unroll
                    for (int r = 0; r < 2; ++r)
#pragma unroll
                        for (int c = 0; c < 4; ++c) acc[r][c] = make_float2(0.f, 0.f);
                }
                if (i + 1 < 64) cp_wait1(); else cp_wait0();
                __syncthreads();
                if (i + 2 < 64) {
                    int ni = i + 2;
                    int sub = ni & 7;
                    const float* Ab = (sub < 4) ? h0c : h1r;
                    issue_Ad(stg[ni % 3],
                             Ab + (size_t)(dRow0 + (ni >> 3) * 128) * HID,
                             (sub & 3) * 64, tid);
                    cp_commit();
                }
                {
                    int sub = i & 7;
                    const float4* wr = (sub < 4) ? W1f : W2f;
                    gemm_chunk<128, 2, 16>(stg[i % 3], wr + (sub & 3) * 16 * 32,
                                           acc, ty, tx);
                }

                if ((i & 7) == 7) {
                    int base = dRow0 + (i >> 3) * 128;
#pragma unroll
                    for (int r = 0; r < 2; ++r) {
                        int row = base + ty + 64 * r;
                        float gi = acc[r][0].x + acc[r][0].y + d_bv1[0];
                        float gf = acc[r][1].x + acc[r][1].y + d_bv1[1];
                        float gg = acc[r][2].x + acc[r][2].y + d_bv1[2];
                        float go = acc[r][3].x + acc[r][3].y + d_bv1[3];
                        int idx = row * HID + j0 + tx;
                        float cn = sigm(gf) * g_dc1[idx] + sigm(gi) * tanhf(gg);
                        g_dc1[idx] = cn;
                        float h = sigm(go) * tanhf(cn);
                        g_dh1[wp][idx] = h;
                        float part = h * outw;
                        part += __shfl_xor_sync(0xffffffffu, part, 1);
                        part += __shfl_xor_sync(0xffffffffu, part, 2);
                        part += __shfl_xor_sync(0xffffffffu, part, 4);
                        if (tx == 0) atomicAdd(&g_pred[wp][row], part);
                    }
                }
            }
        }
        gsync();
    }

    // ---- tail: write out for t = HOR-1 ----
    if (tid < 32) {
        int row = blockIdx.x * 32 + tid;
        float v = __ldcg(&g_pred[(HOR - 1) & 1][row]) + outbv;
        out[(size_t)(row & 255) * (NS * HOR) + (row >> 8) * HOR + (HOR - 1)] = v;
    }
}

// ---------------------------------------------------------------------------
extern "C" void kernel_launch(void* const* d_in, const int* in_sizes, int n_in,
                              void* d_out, int out_size)
{
    (void)in_sizes; (void)n_in; (void)out_size;
    const float* x     = (const float*)d_in[0];
    const float* eWih0 = (const float*)d_in[1];
    const float* eWhh0 = (const float*)d_in[2];
    const float* eb0   = (const float*)d_in[3];
    const float* eWih1 = (const float*)d_in[4];
    const float* eWhh1 = (const float*)d_in[5];
    const float* eb1   = (const float*)d_in[6];
    const float* dWih0 = (const float*)d_in[7];
    const float* dWhh0 = (const float*)d_in[8];
    const float* db0   = (const float*)d_in[9];
    const float* dWih1 = (const float*)d_in[10];
    const float* dWhh1 = (const float*)d_in[11];
    const float* db1   = (const float*)d_in[12];
    const float* outW  = (const float*)d_in[13];
    const float* outb  = (const float*)d_in[14];
    const float* dinit = (const float*)d_in[15];
    float* out = (float*)d_out;

    cudaFuncSetAttribute(lstm_all, cudaFuncAttributeMaxDynamicSharedMemorySize,
                         SMEM_BYTES);

    lstm_all<<<GRID, NTHR, SMEM_BYTES>>>(x, eWih0, eWhh0, eb0, eWih1, eWhh1, eb1,
                                         dWih0, dWhh0, db0, dWih1, dWhh1, db1,
                                         outW, outb, dinit, out);
}

// round 7
// speedup vs baseline: 1.8999x; 1.8999x over previous
#include <cuda_runtime.h>

// ---------------------------------------------------------------------------
// Seq2seq LSTM, ONE persistent kernel, GRID=128 (1 CTA/SM), software barrier.
// Round 7: R5 tile geometry (256 thr, 16 j-cols, RB=8 decoder) but with the
// staging machinery removed:
//   - W resident in smem (3 x 64KB), read-only -> NO syncthreads in k-loops
//   - A (h-state) streamed GMEM->regs via __ldcg (L2-resident), distance-2
//     register double-buffer prefetch. No cp.async, no stages, no bubbles.
//   - gate-spread register-only epilogues, fused projection, skewed encoder.
// ---------------------------------------------------------------------------

#define HID   256
#define BATCH 256
#define TLEN  512
#define NS    16
#define SBAT  4096
#define HOR   64
#define GRID  128
#define NTHR  256
#define PAD   16            // prefetch overread pad (floats)

#define WREG       65536    // one W region: 4 gates x 16 j x 256 K x 4B
#define SMEM_BYTES (3 * WREG)   // 192KB

// ---------------- device state (padded for prefetch overread) ---------------
__device__ float g_eh0[2][BATCH * HID + PAD];
__device__ float g_ec0[BATCH * HID + PAD];
__device__ float g_eh1[2][BATCH * HID + PAD];
__device__ float g_ec1[BATCH * HID + PAD];

__device__ float g_dh0[2][SBAT * HID + PAD];
__device__ float g_dc0[SBAT * HID + PAD];
__device__ float g_dh1[2][SBAT * HID + PAD];
__device__ float g_dc1[SBAT * HID + PAD];
__device__ float g_pred[2][SBAT];

__device__ unsigned g_cnt = 0;
__device__ volatile unsigned g_gen = 0;

// ---------------- grid-wide barrier ------------------------------------------
__device__ __forceinline__ void gsync() {
    __syncthreads();
    if (threadIdx.x == 0) {
        __threadfence();
        unsigned old = g_gen;
        unsigned arrived = atomicAdd(&g_cnt, 1u);
        if (arrived == gridDim.x - 1) {
            g_cnt = 0;
            __threadfence();
            g_gen = old + 1u;
        } else {
            while (g_gen == old) { }
            __threadfence();
        }
    }
    __syncthreads();
}

// ---------------- packed f32x2 FMA -------------------------------------------
union F2U { float2 f; unsigned long long u; };

__device__ __forceinline__ float2 ffma2(float2 a, float2 b, float2 c) {
    F2U ua, ub, uc;
    ua.f = a; ub.f = b; uc.f = c;
    asm("fma.rn.f32x2 %0, %1, %2, %0;" : "+l"(uc.u) : "l"(ua.u), "l"(ub.u));
    return uc.f;
}

__device__ __forceinline__ float sigm(float x) {
    return 1.0f / (1.0f + expf(-x));
}

// ---------------- one-time W region load (cp.async, one-time cost) -----------
__device__ __forceinline__ void cpa16(void* dst, const void* src) {
    unsigned d = (unsigned)__cvta_generic_to_shared(dst);
    asm volatile("cp.async.cg.shared.global [%0], [%1], 16;" :: "r"(d), "l"(src));
}
__device__ __forceinline__ void cp_commit() {
    asm volatile("cp.async.commit_group;" ::: "memory");
}
__device__ __forceinline__ void cp_wait0() {
    asm volatile("cp.async.wait_group 0;" ::: "memory");
}

// W layout: Wf[k4*64 + gate*16 + jj] (float4 = 4 consecutive K of one W row).
// Read side: lanes tx 0..15 hit 256B contiguous -> 2 wavefronts (HW minimum).
__device__ __forceinline__ void load_W_region(char* dst, const float* __restrict__ W,
                                              int j0, int tid) {
    float4* Wf = (float4*)dst;
#pragma unroll
    for (int i = tid; i < 4096; i += NTHR) {
        int k4 = i & 63, s = i >> 6;
        int gate = s >> 4, jj = s & 15;
        cpa16(&Wf[k4 * 64 + s], W + (size_t)(gate * HID + j0 + jj) * HID + k4 * 4);
    }
}

// ---------------------------------------------------------------------------
// GEMM over K=256 (64 k4 steps), no syncs. Thread (ty=tid>>4, tx=tid&15):
// rows rowBase + ty + 16r (r<RB), col j0+tx for all 4 gates.
//   A: __ldcg GMEM->regs, distance-2 double buffer (2 distinct rows/warp ->
//      broadcast sectors, L2-served)
//   W: LDS from resident region, 2 wavefronts each (HW min)
// ---------------------------------------------------------------------------
template<int RB>
__device__ __forceinline__ void gemm256(const float4* __restrict__ Wf,
                                        const float* __restrict__ A,
                                        int rowBase, float2 (&acc)[RB][4],
                                        int ty, int tx)
{
    const float4* __restrict__ Ap =
        reinterpret_cast<const float4*>(A) + (size_t)(rowBase + ty) * 64;
    float4 abuf[2][RB];
#pragma unroll
    for (int r = 0; r < RB; ++r) {
        abuf[0][r] = __ldcg(Ap + r * 1024);
        abuf[1][r] = __ldcg(Ap + r * 1024 + 1);
    }
#pragma unroll 4
    for (int k4 = 0; k4 < 64; ++k4) {
        float4 a[RB];
#pragma unroll
        for (int r = 0; r < RB; ++r) a[r] = abuf[k4 & 1][r];
        if (k4 < 62) {
#pragma unroll
            for (int r = 0; r < RB; ++r)
                abuf[k4 & 1][r] = __ldcg(Ap + r * 1024 + k4 + 2);
        }
        const float4* bp = Wf + k4 * 64 + tx;
        float4 b4[4];
#pragma unroll
        for (int c = 0; c < 4; ++c) b4[c] = bp[c * 16];
#pragma unroll
        for (int r = 0; r < RB; ++r)
#pragma unroll
            for (int c = 0; c < 4; ++c) {
                acc[r][c] = ffma2(make_float2(a[r].x, a[r].y),
                                  make_float2(b4[c].x, b4[c].y), acc[r][c]);
                acc[r][c] = ffma2(make_float2(a[r].z, a[r].w),
                                  make_float2(b4[c].z, b4[c].w), acc[r][c]);
            }
    }
}

// ---------------------------------------------------------------------------
__global__ void __launch_bounds__(NTHR, 1)
lstm_all(const float* __restrict__ x,
         const float* __restrict__ eWih0, const float* __restrict__ eWhh0,
         const float* __restrict__ eb0,
         const float* __restrict__ eWih1, const float* __restrict__ eWhh1,
         const float* __restrict__ eb1,
         const float* __restrict__ dWih0, const float* __restrict__ dWhh0,
         const float* __restrict__ db0,
         const float* __restrict__ dWih1, const float* __restrict__ dWhh1,
         const float* __restrict__ db1,
         const float* __restrict__ outW, const float* __restrict__ outb,
         const float* __restrict__ dinit,
         float* __restrict__ out)
{
    extern __shared__ char smem[];
    const int tid = threadIdx.x;
    const int ty = tid >> 4, tx = tid & 15;     // 16 x 16
    const int jt  = blockIdx.x >> 3;            // 0..15 fixed j-tile
    const int j0  = jt * 16;
    const int grp = blockIdx.x & 7;             // row group
    const int eRow0 = grp * 32;                 // encoder rows (32/CTA)
    const int dRow0 = grp * 512;                // decoder rows (512/CTA)

    const float4* W0f = (const float4*)(smem);
    const float4* W1f = (const float4*)(smem + WREG);
    const float4* W2f = (const float4*)(smem + 2 * WREG);

    // ---- per-thread constants (fixed j column) ----
    float e_bv0[4], e_wv0[4], e_bv1[4];
#pragma unroll
    for (int c = 0; c < 4; ++c) {
        int gr = c * HID + j0 + tx;
        e_bv0[c] = eb0[gr];
        e_wv0[c] = eWih0[gr];
        e_bv1[c] = eb1[gr];
    }

    // ---- resident encoder weights + zero-init state ----
    load_W_region(smem,            eWhh0, j0, tid);
    load_W_region(smem + WREG,     eWih1, j0, tid);
    load_W_region(smem + 2 * WREG, eWhh1, j0, tid);
    cp_commit();
    for (int i = blockIdx.x * NTHR + tid; i < BATCH * HID; i += GRID * NTHR) {
        g_eh0[1][i] = 0.f; g_ec0[i] = 0.f;
        g_eh1[1][i] = 0.f; g_ec1[i] = 0.f;
    }
    cp_wait0();
    gsync();

    // =========================== encoder (skewed) ===========================
    // phase p: L0(t=p) on h0(p-1) [p<TLEN]; L1(t'=p-1) on h0(p-1), h1(p-2)
    // [p>0]. h0(q) lives in buffer q&1; h1(q) in buffer (q+1)&1... (see epis).
    for (int p = 0; p <= TLEN; ++p) {
        const float* hA  = g_eh0[(p + 1) & 1];   // h0(p-1)
        const float* h1r = g_eh1[p & 1];         // h1(p-2)

        if (p < TLEN) {
            float2 acc[2][4];
#pragma unroll
            for (int r = 0; r < 2; ++r)
#pragma unroll
                for (int c = 0; c < 4; ++c) acc[r][c] = make_float2(0.f, 0.f);
            gemm256<2>(W0f, hA, eRow0, acc, ty, tx);
#pragma unroll
            for (int r = 0; r < 2; ++r) {
                int row = eRow0 + ty + 16 * r;
                float xv = x[(size_t)row * TLEN + p];
                float gi = acc[r][0].x + acc[r][0].y + e_bv0[0] + xv * e_wv0[0];
                float gf = acc[r][1].x + acc[r][1].y + e_bv0[1] + xv * e_wv0[1];
                float gg = acc[r][2].x + acc[r][2].y + e_bv0[2] + xv * e_wv0[2];
                float go = acc[r][3].x + acc[r][3].y + e_bv0[3] + xv * e_wv0[3];
                int idx = row * HID + j0 + tx;
                float cn = sigm(gf) * g_ec0[idx] + sigm(gi) * tanhf(gg);
                g_ec0[idx] = cn;
                g_eh0[p & 1][idx] = sigm(go) * tanhf(cn);
            }
        }
        if (p > 0) {
            float2 acc[2][4];
#pragma unroll
            for (int r = 0; r < 2; ++r)
#pragma unroll
                for (int c = 0; c < 4; ++c) acc[r][c] = make_float2(0.f, 0.f);
            gemm256<2>(W1f, hA,  eRow0, acc, ty, tx);
            gemm256<2>(W2f, h1r, eRow0, acc, ty, tx);
#pragma unroll
            for (int r = 0; r < 2; ++r) {
                int row = eRow0 + ty + 16 * r;
                float gi = acc[r][0].x + acc[r][0].y + e_bv1[0];
                float gf = acc[r][1].x + acc[r][1].y + e_bv1[1];
                float gg = acc[r][2].x + acc[r][2].y + e_bv1[2];
                float go = acc[r][3].x + acc[r][3].y + e_bv1[3];
                int idx = row * HID + j0 + tx;
                float cn = sigm(gf) * g_ec1[idx] + sigm(gi) * tanhf(gg);
                g_ec1[idx] = cn;
                g_eh1[(p + 1) & 1][idx] = sigm(go) * tanhf(cn);
            }
        }
        gsync();
    }

    // ============== decoder setup: W reload + state broadcast ================
    load_W_region(smem,            dWhh0, j0, tid);
    load_W_region(smem + WREG,     dWih1, j0, tid);
    load_W_region(smem + 2 * WREG, dWhh1, j0, tid);
    cp_commit();
    for (int i = blockIdx.x * NTHR + tid; i < SBAT * HID; i += GRID * NTHR) {
        int src = i & (BATCH * HID - 1);
        g_dh0[1][i] = __ldcg(&g_eh0[1][src]);
        g_dc0[i]    = __ldcg(&g_ec0[src]);
        g_dh1[1][i] = __ldcg(&g_eh1[1][src]);
        g_dc1[i]    = __ldcg(&g_ec1[src]);
    }
    cp_wait0();
    gsync();

    float d_bv0[4], d_wv0[4], d_bv1[4];
#pragma unroll
    for (int c = 0; c < 4; ++c) {
        int gr = c * HID + j0 + tx;
        d_bv0[c] = db0[gr];
        d_wv0[c] = dWih0[gr];
        d_bv1[c] = db1[gr];
    }
    const float outw  = outW[j0 + tx];
    const float outbv = outb[0];

    // =========================== decoder =====================================
    // Per CTA per phase: 4 row tiles of 128 (RB=8), K=256 (L0) / 512 (L1).
    for (int t = 0; t < HOR; ++t) {
        const int rp = (t + 1) & 1, wp = t & 1;

        // ---- layer0 ----
        if (tid < 32) g_pred[wp][blockIdx.x * 32 + tid] = 0.f;
        {
            const float* h0r = g_dh0[rp];
            for (int tile = 0; tile < 4; ++tile) {
                int base = dRow0 + tile * 128;
                float2 acc[8][4];
#pragma unroll
                for (int r = 0; r < 8; ++r)
#pragma unroll
                    for (int c = 0; c < 4; ++c) acc[r][c] = make_float2(0.f, 0.f);
                gemm256<8>(W0f, h0r, base, acc, ty, tx);
#pragma unroll
                for (int r = 0; r < 8; ++r) {
                    int row = base + ty + 16 * r;
                    float iv;
                    if (t == 0) {
                        iv = dinit[row];
                    } else {
                        iv = __ldcg(&g_pred[rp][row]) + outbv;
                        if (jt == 0 && tx == 0)
                            out[(size_t)(row & 255) * (NS * HOR)
                                + (row >> 8) * HOR + (t - 1)] = iv;
                    }
                    float gi = acc[r][0].x + acc[r][0].y + d_bv0[0] + iv * d_wv0[0];
                    float gf = acc[r][1].x + acc[r][1].y + d_bv0[1] + iv * d_wv0[1];
                    float gg = acc[r][2].x + acc[r][2].y + d_bv0[2] + iv * d_wv0[2];
                    float go = acc[r][3].x + acc[r][3].y + d_bv0[3] + iv * d_wv0[3];
                    int idx = row * HID + j0 + tx;
                    float cn = sigm(gf) * g_dc0[idx] + sigm(gi) * tanhf(gg);
                    g_dc0[idx] = cn;
                    g_dh0[wp][idx] = sigm(go) * tanhf(cn);
                }
            }
        }
        gsync();

        // ---- layer1 (+ fused projection) ----
        {
            const float* h0c = g_dh0[wp];
            const float* h1r = g_dh1[rp];
            for (int tile = 0; tile < 4; ++tile) {
                int base = dRow0 + tile * 128;
                float2 acc[8][4];
#pragma unroll
                for (int r = 0; r < 8; ++r)
#pragma unroll
                    for (int c = 0; c < 4; ++c) acc[r][c] = make_float2(0.f, 0.f);
                gemm256<8>(W1f, h0c, base, acc, ty, tx);
                gemm256<8>(W2f, h1r, base, acc, ty, tx);
#pragma unroll
                for (int r = 0; r < 8; ++r) {
                    int row = base + ty + 16 * r;
                    float gi = acc[r][0].x + acc[r][0].y + d_bv1[0];
                    float gf = acc[r][1].x + acc[r][1].y + d_bv1[1];
                    float gg = acc[r][2].x + acc[r][2].y + d_bv1[2];
                    float go = acc[r][3].x + acc[r][3].y + d_bv1[3];
                    int idx = row * HID + j0 + tx;
                    float cn = sigm(gf) * g_dc1[idx] + sigm(gi) * tanhf(gg);
                    g_dc1[idx] = cn;
                    float h = sigm(go) * tanhf(cn);
                    g_dh1[wp][idx] = h;
                    float part = h * outw;
                    part += __shfl_xor_sync(0xffffffffu, part, 1);
                    part += __shfl_xor_sync(0xffffffffu, part, 2);
                    part += __shfl_xor_sync(0xffffffffu, part, 4);
                    part += __shfl_xor_sync(0xffffffffu, part, 8);
                    if (tx == 0) atomicAdd(&g_pred[wp][row], part);
                }
            }
        }
        gsync();
    }

    // ---- tail: write out for t = HOR-1 ----
    if (tid < 32) {
        int row = blockIdx.x * 32 + tid;
        float v = __ldcg(&g_pred[(HOR - 1) & 1][row]) + outbv;
        out[(size_t)(row & 255) * (NS * HOR) + (row >> 8) * HOR + (HOR - 1)] = v;
    }
}

// ---------------------------------------------------------------------------
extern "C" void kernel_launch(void* const* d_in, const int* in_sizes, int n_in,
                              void* d_out, int out_size)
{
    (void)in_sizes; (void)n_in; (void)out_size;
    const float* x     = (const float*)d_in[0];
    const float* eWih0 = (const float*)d_in[1];
    const float* eWhh0 = (const float*)d_in[2];
    const float* eb0   = (const float*)d_in[3];
    const float* eWih1 = (const float*)d_in[4];
    const float* eWhh1 = (const float*)d_in[5];
    const float* eb1   = (const float*)d_in[6];
    const float* dWih0 = (const float*)d_in[7];
    const float* dWhh0 = (const float*)d_in[8];
    const float* db0   = (const float*)d_in[9];
    const float* dWih1 = (const float*)d_in[10];
    const float* dWhh1 = (const float*)d_in[11];
    const float* db1   = (const float*)d_in[12];
    const float* outW  = (const float*)d_in[13];
    const float* outb  = (const float*)d_in[14];
    const float* dinit = (const float*)d_in[15];
    float* out = (float*)d_out;

    cudaFuncSetAttribute(lstm_all, cudaFuncAttributeMaxDynamicSharedMemorySize,
                         SMEM_BYTES);

    lstm_all<<<GRID, NTHR, SMEM_BYTES>>>(x, eWih0, eWhh0, eb0, eWih1, eWhh1, eb1,
                                         dWih0, dWhh0, db0, dWih1, dWhh1, db1,
                                         outW, outb, dinit, out);
}

// round 8
// speedup vs baseline: 1.9012x; 1.0007x over previous
#include <cuda_runtime.h>

// ---------------------------------------------------------------------------
// Seq2seq LSTM, ONE persistent kernel, GRID=128 (1 CTA/SM), software barrier.
// Round 7: R5 tile geometry (256 thr, 16 j-cols, RB=8 decoder) but with the
// staging machinery removed:
//   - W resident in smem (3 x 64KB), read-only -> NO syncthreads in k-loops
//   - A (h-state) streamed GMEM->regs via __ldcg (L2-resident), distance-2
//     register double-buffer prefetch. No cp.async, no stages, no bubbles.
//   - gate-spread register-only epilogues, fused projection, skewed encoder.
// ---------------------------------------------------------------------------

#define HID   256
#define BATCH 256
#define TLEN  512
#define NS    16
#define SBAT  4096
#define HOR   64
#define GRID  128
#define NTHR  256
#define PAD   16            // prefetch overread pad (floats)

#define WREG       65536    // one W region: 4 gates x 16 j x 256 K x 4B
#define SMEM_BYTES (3 * WREG)   // 192KB

// ---------------- device state (padded for prefetch overread) ---------------
__device__ float g_eh0[2][BATCH * HID + PAD];
__device__ float g_ec0[BATCH * HID + PAD];
__device__ float g_eh1[2][BATCH * HID + PAD];
__device__ float g_ec1[BATCH * HID + PAD];

__device__ float g_dh0[2][SBAT * HID + PAD];
__device__ float g_dc0[SBAT * HID + PAD];
__device__ float g_dh1[2][SBAT * HID + PAD];
__device__ float g_dc1[SBAT * HID + PAD];
__device__ float g_pred[2][SBAT];

__device__ unsigned g_cnt = 0;
__device__ volatile unsigned g_gen = 0;

// ---------------- grid-wide barrier ------------------------------------------
__device__ __forceinline__ void gsync() {
    __syncthreads();
    if (threadIdx.x == 0) {
        __threadfence();
        unsigned old = g_gen;
        unsigned arrived = atomicAdd(&g_cnt, 1u);
        if (arrived == gridDim.x - 1) {
            g_cnt = 0;
            __threadfence();
            g_gen = old + 1u;
        } else {
            while (g_gen == old) { }
            __threadfence();
        }
    }
    __syncthreads();
}

// ---------------- packed f32x2 FMA -------------------------------------------
union F2U { float2 f; unsigned long long u; };

__device__ __forceinline__ float2 ffma2(float2 a, float2 b, float2 c) {
    F2U ua, ub, uc;
    ua.f = a; ub.f = b; uc.f = c;
    asm("fma.rn.f32x2 %0, %1, %2, %0;" : "+l"(uc.u) : "l"(ua.u), "l"(ub.u));
    return uc.f;
}

__device__ __forceinline__ float sigm(float x) {
    return 1.0f / (1.0f + expf(-x));
}

// ---------------- one-time W region load (cp.async, one-time cost) -----------
__device__ __forceinline__ void cpa16(void* dst, const void* src) {
    unsigned d = (unsigned)__cvta_generic_to_shared(dst);
    asm volatile("cp.async.cg.shared.global [%0], [%1], 16;" :: "r"(d), "l"(src));
}
__device__ __forceinline__ void cp_commit() {
    asm volatile("cp.async.commit_group;" ::: "memory");
}
__device__ __forceinline__ void cp_wait0() {
    asm volatile("cp.async.wait_group 0;" ::: "memory");
}

// W layout: Wf[k4*64 + gate*16 + jj] (float4 = 4 consecutive K of one W row).
// Read side: lanes tx 0..15 hit 256B contiguous -> 2 wavefronts (HW minimum).
__device__ __forceinline__ void load_W_region(char* dst, const float* __restrict__ W,
                                              int j0, int tid) {
    float4* Wf = (float4*)dst;
#pragma unroll
    for (int i = tid; i < 4096; i += NTHR) {
        int k4 = i & 63, s = i >> 6;
        int gate = s >> 4, jj = s & 15;
        cpa16(&Wf[k4 * 64 + s], W + (size_t)(gate * HID + j0 + jj) * HID + k4 * 4);
    }
}

// ---------------------------------------------------------------------------
// GEMM over K=256 (64 k4 steps), no syncs. Thread (ty=tid>>4, tx=tid&15):
// rows rowBase + ty + 16r (r<RB), col j0+tx for all 4 gates.
//   A: __ldcg GMEM->regs, distance-2 double buffer (2 distinct rows/warp ->
//      broadcast sectors, L2-served)
//   W: LDS from resident region, 2 wavefronts each (HW min)
// ---------------------------------------------------------------------------
template<int RB>
__device__ __forceinline__ void gemm256(const float4* __restrict__ Wf,
                                        const float* __restrict__ A,
                                        int rowBase, float2 (&acc)[RB][4],
                                        int ty, int tx)
{
    const float4* __restrict__ Ap =
        reinterpret_cast<const float4*>(A) + (size_t)(rowBase + ty) * 64;
    float4 abuf[2][RB];
#pragma unroll
    for (int r = 0; r < RB; ++r) {
        abuf[0][r] = __ldcg(Ap + r * 1024);
        abuf[1][r] = __ldcg(Ap + r * 1024 + 1);
    }
#pragma unroll 4
    for (int k4 = 0; k4 < 64; ++k4) {
        float4 a[RB];
#pragma unroll
        for (int r = 0; r < RB; ++r) a[r] = abuf[k4 & 1][r];
        if (k4 < 62) {
#pragma unroll
            for (int r = 0; r < RB; ++r)
                abuf[k4 & 1][r] = __ldcg(Ap + r * 1024 + k4 + 2);
        }
        const float4* bp = Wf + k4 * 64 + tx;
        float4 b4[4];
#pragma unroll
        for (int c = 0; c < 4; ++c) b4[c] = bp[c * 16];
#pragma unroll
        for (int r = 0; r < RB; ++r)
#pragma unroll
            for (int c = 0; c < 4; ++c) {
                acc[r][c] = ffma2(make_float2(a[r].x, a[r].y),
                                  make_float2(b4[c].x, b4[c].y), acc[r][c]);
                acc[r][c] = ffma2(make_float2(a[r].z, a[r].w),
                                  make_float2(b4[c].z, b4[c].w), acc[r][c]);
            }
    }
}

// ---------------------------------------------------------------------------
__global__ void __launch_bounds__(NTHR, 1)
lstm_all(const float* __restrict__ x,
         const float* __restrict__ eWih0, const float* __restrict__ eWhh0,
         const float* __restrict__ eb0,
         const float* __restrict__ eWih1, const float* __restrict__ eWhh1,
         const float* __restrict__ eb1,
         const float* __restrict__ dWih0, const float* __restrict__ dWhh0,
         const float* __restrict__ db0,
         const float* __restrict__ dWih1, const float* __restrict__ dWhh1,
         const float* __restrict__ db1,
         const float* __restrict__ outW, const float* __restrict__ outb,
         const float* __restrict__ dinit,
         float* __restrict__ out)
{
    extern __shared__ char smem[];
    const int tid = threadIdx.x;
    const int ty = tid >> 4, tx = tid & 15;     // 16 x 16
    const int jt  = blockIdx.x >> 3;            // 0..15 fixed j-tile
    const int j0  = jt * 16;
    const int grp = blockIdx.x & 7;             // row group
    const int eRow0 = grp * 32;                 // encoder rows (32/CTA)
    const int dRow0 = grp * 512;                // decoder rows (512/CTA)

    const float4* W0f = (const float4*)(smem);
    const float4* W1f = (const float4*)(smem + WREG);
    const float4* W2f = (const float4*)(smem + 2 * WREG);

    // ---- per-thread constants (fixed j column) ----
    float e_bv0[4], e_wv0[4], e_bv1[4];
#pragma unroll
    for (int c = 0; c < 4; ++c) {
        int gr = c * HID + j0 + tx;
        e_bv0[c] = eb0[gr];
        e_wv0[c] = eWih0[gr];
        e_bv1[c] = eb1[gr];
    }

    // ---- resident encoder weights + zero-init state ----
    load_W_region(smem,            eWhh0, j0, tid);
    load_W_region(smem + WREG,     eWih1, j0, tid);
    load_W_region(smem + 2 * WREG, eWhh1, j0, tid);
    cp_commit();
    for (int i = blockIdx.x * NTHR + tid; i < BATCH * HID; i += GRID * NTHR) {
        g_eh0[1][i] = 0.f; g_ec0[i] = 0.f;
        g_eh1[1][i] = 0.f; g_ec1[i] = 0.f;
    }
    cp_wait0();
    gsync();

    // =========================== encoder (skewed) ===========================
    // phase p: L0(t=p) on h0(p-1) [p<TLEN]; L1(t'=p-1) on h0(p-1), h1(p-2)
    // [p>0]. h0(q) lives in buffer q&1; h1(q) in buffer (q+1)&1... (see epis).
    for (int p = 0; p <= TLEN; ++p) {
        const float* hA  = g_eh0[(p + 1) & 1];   // h0(p-1)
        const float* h1r = g_eh1[p & 1];         // h1(p-2)

        if (p < TLEN) {
            float2 acc[2][4];
#pragma unroll
            for (int r = 0; r < 2; ++r)
#pragma unroll
                for (int c = 0; c < 4; ++c) acc[r][c] = make_float2(0.f, 0.f);
            gemm256<2>(W0f, hA, eRow0, acc, ty, tx);
#pragma unroll
            for (int r = 0; r < 2; ++r) {
                int row = eRow0 + ty + 16 * r;
                float xv = x[(size_t)row * TLEN + p];
                float gi = acc[r][0].x + acc[r][0].y + e_bv0[0] + xv * e_wv0[0];
                float gf = acc[r][1].x + acc[r][1].y + e_bv0[1] + xv * e_wv0[1];
                float gg = acc[r][2].x + acc[r][2].y + e_bv0[2] + xv * e_wv0[2];
                float go = acc[r][3].x + acc[r][3].y + e_bv0[3] + xv * e_wv0[3];
                int idx = row * HID + j0 + tx;
                float cn = sigm(gf) * g_ec0[idx] + sigm(gi) * tanhf(gg);
                g_ec0[idx] = cn;
                g_eh0[p & 1][idx] = sigm(go) * tanhf(cn);
            }
        }
        if (p > 0) {
            float2 acc[2][4];
#pragma unroll
            for (int r = 0; r < 2; ++r)
#pragma unroll
                for (int c = 0; c < 4; ++c) acc[r][c] = make_float2(0.f, 0.f);
            gemm256<2>(W1f, hA,  eRow0, acc, ty, tx);
            gemm256<2>(W2f, h1r, eRow0, acc, ty, tx);
#pragma unroll
            for (int r = 0; r < 2; ++r) {
                int row = eRow0 + ty + 16 * r;
                float gi = acc[r][0].x + acc[r][0].y + e_bv1[0];
                float gf = acc[r][1].x + acc[r][1].y + e_bv1[1];
                float gg = acc[r][2].x + acc[r][2].y + e_bv1[2];
                float go = acc[r][3].x + acc[r][3].y + e_bv1[3];
                int idx = row * HID + j0 + tx;
                float cn = sigm(gf) * g_ec1[idx] + sigm(gi) * tanhf(gg);
                g_ec1[idx] = cn;
                g_eh1[(p + 1) & 1][idx] = sigm(go) * tanhf(cn);
            }
        }
        gsync();
    }

    // ============== decoder setup: W reload + state broadcast ================
    load_W_region(smem,            dWhh0, j0, tid);
    load_W_region(smem + WREG,     dWih1, j0, tid);
    load_W_region(smem + 2 * WREG, dWhh1, j0, tid);
    cp_commit();
    for (int i = blockIdx.x * NTHR + tid; i < SBAT * HID; i += GRID * NTHR) {
        int src = i & (BATCH * HID - 1);
        g_dh0[1][i] = __ldcg(&g_eh0[1][src]);
        g_dc0[i]    = __ldcg(&g_ec0[src]);
        g_dh1[1][i] = __ldcg(&g_eh1[1][src]);
        g_dc1[i]    = __ldcg(&g_ec1[src]);
    }
    cp_wait0();
    gsync();

    float d_bv0[4], d_wv0[4], d_bv1[4];
#pragma unroll
    for (int c = 0; c < 4; ++c) {
        int gr = c * HID + j0 + tx;
        d_bv0[c] = db0[gr];
        d_wv0[c] = dWih0[gr];
        d_bv1[c] = db1[gr];
    }
    const float outw  = outW[j0 + tx];
    const float outbv = outb[0];

    // =========================== decoder =====================================
    // Per CTA per phase: 4 row tiles of 128 (RB=8), K=256 (L0) / 512 (L1).
    for (int t = 0; t < HOR; ++t) {
        const int rp = (t + 1) & 1, wp = t & 1;

        // ---- layer0 ----
        if (tid < 32) g_pred[wp][blockIdx.x * 32 + tid] = 0.f;
        {
            const float* h0r = g_dh0[rp];
            for (int tile = 0; tile < 4; ++tile) {
                int base = dRow0 + tile * 128;
                float2 acc[8][4];
#pragma unroll
                for (int r = 0; r < 8; ++r)
#pragma unroll
                    for (int c = 0; c < 4; ++c) acc[r][c] = make_float2(0.f, 0.f);
                gemm256<8>(W0f, h0r, base, acc, ty, tx);
#pragma unroll
                for (int r = 0; r < 8; ++r) {
                    int row = base + ty + 16 * r;
                    float iv;
                    if (t == 0) {
                        iv = dinit[row];
                    } else {
                        iv = __ldcg(&g_pred[rp][row]) + outbv;
                        if (jt == 0 && tx == 0)
                            out[(size_t)(row & 255) * (NS * HOR)
                                + (row >> 8) * HOR + (t - 1)] = iv;
                    }
                    float gi = acc[r][0].x + acc[r][0].y + d_bv0[0] + iv * d_wv0[0];
                    float gf = acc[r][1].x + acc[r][1].y + d_bv0[1] + iv * d_wv0[1];
                    float gg = acc[r][2].x + acc[r][2].y + d_bv0[2] + iv * d_wv0[2];
                    float go = acc[r][3].x + acc[r][3].y + d_bv0[3] + iv * d_wv0[3];
                    int idx = row * HID + j0 + tx;
                    float cn = sigm(gf) * g_dc0[idx] + sigm(gi) * tanhf(gg);
                    g_dc0[idx] = cn;
                    g_dh0[wp][idx] = sigm(go) * tanhf(cn);
                }
            }
        }
        gsync();

        // ---- layer1 (+ fused projection) ----
        {
            const float* h0c = g_dh0[wp];
            const float* h1r = g_dh1[rp];
            for (int tile = 0; tile < 4; ++tile) {
                int base = dRow0 + tile * 128;
                float2 acc[8][4];
#pragma unroll
                for (int r = 0; r < 8; ++r)
#pragma unroll
                    for (int c = 0; c < 4; ++c) acc[r][c] = make_float2(0.f, 0.f);
                gemm256<8>(W1f, h0c, base, acc, ty, tx);
                gemm256<8>(W2f, h1r, base, acc, ty, tx);
#pragma unroll
                for (int r = 0; r < 8; ++r) {
                    int row = base + ty + 16 * r;
                    float gi = acc[r][0].x + acc[r][0].y + d_bv1[0];
                    float gf = acc[r][1].x + acc[r][1].y + d_bv1[1];
                    float gg = acc[r][2].x + acc[r][2].y + d_bv1[2];
                    float go = acc[r][3].x + acc[r][3].y + d_bv1[3];
                    int idx = row * HID + j0 + tx;
                    float cn = sigm(gf) * g_dc1[idx] + sigm(gi) * tanhf(gg);
                    g_dc1[idx] = cn;
                    float h = sigm(go) * tanhf(cn);
                    g_dh1[wp][idx] = h;
                    float part = h * outw;
                    part += __shfl_xor_sync(0xffffffffu, part, 1);
                    part += __shfl_xor_sync(0xffffffffu, part, 2);
                    part += __shfl_xor_sync(0xffffffffu, part, 4);
                    part += __shfl_xor_sync(0xffffffffu, part, 8);
                    if (tx == 0) atomicAdd(&g_pred[wp][row], part);
                }
            }
        }
        gsync();
    }

    // ---- tail: write out for t = HOR-1 ----
    if (tid < 32) {
        int row = blockIdx.x * 32 + tid;
        float v = __ldcg(&g_pred[(HOR - 1) & 1][row]) + outbv;
        out[(size_t)(row & 255) * (NS * HOR) + (row >> 8) * HOR + (HOR - 1)] = v;
    }
}

// ---------------------------------------------------------------------------
extern "C" void kernel_launch(void* const* d_in, const int* in_sizes, int n_in,
                              void* d_out, int out_size)
{
    (void)in_sizes; (void)n_in; (void)out_size;
    const float* x     = (const float*)d_in[0];
    const float* eWih0 = (const float*)d_in[1];
    const float* eWhh0 = (const float*)d_in[2];
    const float* eb0   = (const float*)d_in[3];
    const float* eWih1 = (const float*)d_in[4];
    const float* eWhh1 = (const float*)d_in[5];
    const float* eb1   = (const float*)d_in[6];
    const float* dWih0 = (const float*)d_in[7];
    const float* dWhh0 = (const float*)d_in[8];
    const float* db0   = (const float*)d_in[9];
    const float* dWih1 = (const float*)d_in[10];
    const float* dWhh1 = (const float*)d_in[11];
    const float* db1   = (const float*)d_in[12];
    const float* outW  = (const float*)d_in[13];
    const float* outb  = (const float*)d_in[14];
    const float* dinit = (const float*)d_in[15];
    float* out = (float*)d_out;

    cudaFuncSetAttribute(lstm_all, cudaFuncAttributeMaxDynamicSharedMemorySize,
                         SMEM_BYTES);

    lstm_all<<<GRID, NTHR, SMEM_BYTES>>>(x, eWih0, eWhh0, eb0, eWih1, eWhh1, eb1,
                                         dWih0, dWhh0, db0, dWih1, dWhh1, db1,
                                         outW, outb, dinit, out);
}

// round 10
// speedup vs baseline: 2.5491x; 1.3408x over previous
#include <cuda_runtime.h>
#include <cuda_bf16.h>

#define HID   256
#define BATCH 256
#define TLEN  512
#define NS    16
#define SBAT  4096
#define HOR   64
#define GRID  128
#define NTHR  256
#define PAD   16
#define WREG  65536
#define CTRL  196608
#define SMEM_BYTES (CTRL + 1024)

__device__ float g_eh0[2][BATCH * HID + PAD];
__device__ float g_ec0[BATCH * HID + PAD];
__device__ float g_eh1[2][BATCH * HID + PAD];
__device__ float g_ec1[BATCH * HID + PAD];

__device__ float g_dc0[SBAT * HID];
__device__ float g_dc1[SBAT * HID];
__device__ float g_pred[2][SBAT];
__device__ __nv_bfloat16 g_h0b[2][2][SBAT * HID];   // [buf][hi/lo]
__device__ __nv_bfloat16 g_h1b[2][2][SBAT * HID];
__device__ __nv_bfloat16 g_wfrag[3][2][16][16384];  // [mat][part][jt][frag elems]

__device__ unsigned g_cnt = 0;
__device__ volatile unsigned g_gen = 0;

__device__ __forceinline__ void gsync() {
    __syncthreads();
    if (threadIdx.x == 0) {
        __threadfence();
        unsigned old = g_gen;
        unsigned a = atomicAdd(&g_cnt, 1u);
        if (a == gridDim.x - 1) { g_cnt = 0; __threadfence(); g_gen = old + 1u; }
        else { while (g_gen == old) { } __threadfence(); }
    }
    __syncthreads();
}
union F2U { float2 f; unsigned long long u; };
__device__ __forceinline__ float2 ffma2(float2 a, float2 b, float2 c) {
    F2U ua, ub, uc; ua.f = a; ub.f = b; uc.f = c;
    asm("fma.rn.f32x2 %0, %1, %2, %0;" : "+l"(uc.u) : "l"(ua.u), "l"(ub.u));
    return uc.f;
}
__device__ __forceinline__ float sigm(float x) { return 1.0f / (1.0f + expf(-x)); }
__device__ __forceinline__ void bsplit(float v, __nv_bfloat16& h, __nv_bfloat16& l) {
    h = __float2bfloat16(v);
    l = __float2bfloat16(v - __bfloat162float(h));
}
__device__ __forceinline__ void cpa16(void* dst, const void* src) {
    unsigned d = (unsigned)__cvta_generic_to_shared(dst);
    asm volatile("cp.async.cg.shared.global [%0], [%1], 16;" :: "r"(d), "l"(src));
}
__device__ __forceinline__ void cp_commit() { asm volatile("cp.async.commit_group;" ::: "memory"); }
__device__ __forceinline__ void cp_wait0()  { asm volatile("cp.async.wait_group 0;" ::: "memory"); }

// bf16 m16n8k16 HMMA, fp32 accumulate
__device__ __forceinline__ void hmma(float (&d)[4], const unsigned (&a)[4],
                                     unsigned b0, unsigned b1) {
    asm volatile(
        "mma.sync.aligned.m16n8k16.row.col.f32.bf16.bf16.f32 "
        "{%0,%1,%2,%3}, {%4,%5,%6,%7}, {%8,%9}, {%0,%1,%2,%3};"
        : "+f"(d[0]), "+f"(d[1]), "+f"(d[2]), "+f"(d[3])
        : "r"(a[0]), "r"(a[1]), "r"(a[2]), "r"(a[3]), "r"(b0), "r"(b1));
}
// A fragment from row-major bf16 [row][256]: a0={r,k,k+1} a1={r+8} a2={r,k+8} a3={r+8,k+8}
__device__ __forceinline__ void ldA(unsigned (&a)[4], const __nv_bfloat16* base,
                                    int row, int kk) {
    const unsigned* p = (const unsigned*)(base + (size_t)row * HID + kk);
    a[0] = __ldcg(p);
    a[1] = __ldcg(p + 1024);
    a[2] = __ldcg(p + 4);
    a[3] = __ldcg(p + 1028);
}

// K=256 GEMM: acc[4 m16][8 n8][4] += A(64 rows) x Wfrag(64 cols), 3-product split
__device__ __forceinline__ void mma_gemm256(float (&acc)[4][8][4],
    const __nv_bfloat16* __restrict__ Ahi, const __nv_bfloat16* __restrict__ Alo,
    const char* __restrict__ wreg, int wrow, int lane)
{
    const int r4 = lane >> 2, q = lane & 3;
#pragma unroll 2
    for (int k16 = 0; k16 < 16; ++k16) {
        unsigned ah[4][4], al[4][4];
        int kk = k16 * 16 + q * 2;
#pragma unroll
        for (int mi = 0; mi < 4; ++mi) {
            ldA(ah[mi], Ahi, wrow + mi * 16 + r4, kk);
            ldA(al[mi], Alo, wrow + mi * 16 + r4, kk);
        }
#pragma unroll
        for (int n8 = 0; n8 < 8; ++n8) {
            unsigned off = (unsigned)(((k16 * 8 + n8) * 32 + lane) * 8);
            uint2 bh = *(const uint2*)(wreg + off);
            uint2 bl = *(const uint2*)(wreg + 32768 + off);
#pragma unroll
            for (int mi = 0; mi < 4; ++mi) {
                hmma(acc[mi][n8], ah[mi], bh.x, bh.y);
                hmma(acc[mi][n8], ah[mi], bl.x, bl.y);
                hmma(acc[mi][n8], al[mi], bh.x, bh.y);
            }
        }
    }
}

// ---------------- encoder pieces (R7, proven) ---------------------------------
__device__ __forceinline__ void load_W_region(char* dst, const float* __restrict__ W,
                                              int j0, int tid) {
    float4* Wf = (float4*)dst;
    for (int i = tid; i < 4096; i += NTHR) {
        int k4 = i & 63, s = i >> 6;
        int gate = s >> 4, jj = s & 15;
        cpa16(&Wf[k4 * 64 + s], W + (size_t)(gate * HID + j0 + jj) * HID + k4 * 4);
    }
}
template<int RB>
__device__ __forceinline__ void gemm256(const float4* __restrict__ Wf,
                                        const float* __restrict__ A,
                                        int rowBase, float2 (&acc)[RB][4],
                                        int ty, int tx)
{
    const float4* __restrict__ Ap =
        reinterpret_cast<const float4*>(A) + (size_t)(rowBase + ty) * 64;
    float4 abuf[2][RB];
#pragma unroll
    for (int r = 0; r < RB; ++r) {
        abuf[0][r] = __ldcg(Ap + r * 1024);
        abuf[1][r] = __ldcg(Ap + r * 1024 + 1);
    }
#pragma unroll 4
    for (int k4 = 0; k4 < 64; ++k4) {
        float4 a[RB];
#pragma unroll
        for (int r = 0; r < RB; ++r) a[r] = abuf[k4 & 1][r];
        if (k4 < 62) {
#pragma unroll
            for (int r = 0; r < RB; ++r)
                abuf[k4 & 1][r] = __ldcg(Ap + r * 1024 + k4 + 2);
        }
        const float4* bp = Wf + k4 * 64 + tx;
        float4 b4[4];
#pragma unroll
        for (int c = 0; c < 4; ++c) b4[c] = bp[c * 16];
#pragma unroll
        for (int r = 0; r < RB; ++r)
#pragma unroll
            for (int c = 0; c < 4; ++c) {
                acc[r][c] = ffma2(make_float2(a[r].x, a[r].y),
                                  make_float2(b4[c].x, b4[c].y), acc[r][c]);
                acc[r][c] = ffma2(make_float2(a[r].z, a[r].w),
                                  make_float2(b4[c].z, b4[c].w), acc[r][c]);
            }
    }
}

// ---------------------------------------------------------------------------
__global__ void __launch_bounds__(NTHR, 1)
lstm_all(const float* __restrict__ x,
         const float* __restrict__ eWih0, const float* __restrict__ eWhh0,
         const float* __restrict__ eb0,
         const float* __restrict__ eWih1, const float* __restrict__ eWhh1,
         const float* __restrict__ eb1,
         const float* __restrict__ dWih0, const float* __restrict__ dWhh0,
         const float* __restrict__ db0,
         const float* __restrict__ dWih1, const float* __restrict__ dWhh1,
         const float* __restrict__ db1,
         const float* __restrict__ outW, const float* __restrict__ outb,
         const float* __restrict__ dinit,
         float* __restrict__ out)
{
    extern __shared__ char smem[];
    const int tid = threadIdx.x;
    const int w = tid >> 5, lane = tid & 31;
    const int ty = tid >> 4, tx = tid & 15;
    const int jt = blockIdx.x >> 3, j0 = jt * 16;
    const int grp = blockIdx.x & 7, eRow0 = grp * 32, dRow0 = grp * 512;

    const float4* W0f = (const float4*)(smem);
    const float4* W1f = (const float4*)(smem + WREG);
    const float4* W2f = (const float4*)(smem + 2 * WREG);

    float e_bv0[4], e_wv0[4], e_bv1[4];
#pragma unroll
    for (int c = 0; c < 4; ++c) {
        int gr = c * HID + j0 + tx;
        e_bv0[c] = eb0[gr]; e_wv0[c] = eWih0[gr]; e_bv1[c] = eb1[gr];
    }

    // ---- init: encoder W resident, state zero, decoder W fragment images ----
    load_W_region(smem,            eWhh0, j0, tid);
    load_W_region(smem + WREG,     eWih1, j0, tid);
    load_W_region(smem + 2 * WREG, eWhh1, j0, tid);
    cp_commit();
    for (int i = blockIdx.x * NTHR + tid; i < BATCH * HID; i += GRID * NTHR) {
        g_eh0[1][i] = 0.f; g_ec0[i] = 0.f;
        g_eh1[1][i] = 0.f; g_ec1[i] = 0.f;
    }
    {
        const float* Wsrc[3] = { dWhh0, dWih1, dWhh1 };
        for (int idx = blockIdx.x * NTHR + tid; idx < 3 * 32 * 16384;
             idx += GRID * NTHR) {
            int e = idx & 16383;
            int rgn = idx >> 14;              // [m(3)][part(2)][jt(16)]
            int ijt = rgn & 15, part = (rgn >> 4) & 1, m = rgn >> 5;
            int reg = e & 3, ln = (e >> 2) & 31, blk = e >> 7;
            int n8 = blk & 7, k16 = blk >> 3;
            int k = k16 * 16 + (ln & 3) * 2 + (reg & 1) + (reg >> 1) * 8;
            int nl = n8 * 8 + (ln >> 2);
            int gate = nl >> 4, j = nl & 15;
            float v = Wsrc[m][(size_t)(gate * HID + ijt * 16 + j) * HID + k];
            __nv_bfloat16 hh, hl; bsplit(v, hh, hl);
            g_wfrag[m][part][ijt][e] = part ? hl : hh;
        }
    }
    cp_wait0();
    gsync();

    // =========================== encoder (R7, unchanged) ======================
    for (int p = 0; p <= TLEN; ++p) {
        const float* hA  = g_eh0[(p + 1) & 1];
        const float* h1r = g_eh1[p & 1];
        if (p < TLEN) {
            float2 acc[2][4];
#pragma unroll
            for (int r = 0; r < 2; ++r)
#pragma unroll
                for (int c = 0; c < 4; ++c) acc[r][c] = make_float2(0.f, 0.f);
            gemm256<2>(W0f, hA, eRow0, acc, ty, tx);
#pragma unroll
            for (int r = 0; r < 2; ++r) {
                int row = eRow0 + ty + 16 * r;
                float xv = x[(size_t)row * TLEN + p];
                float gi = acc[r][0].x + acc[r][0].y + e_bv0[0] + xv * e_wv0[0];
                float gf = acc[r][1].x + acc[r][1].y + e_bv0[1] + xv * e_wv0[1];
                float gg = acc[r][2].x + acc[r][2].y + e_bv0[2] + xv * e_wv0[2];
                float go = acc[r][3].x + acc[r][3].y + e_bv0[3] + xv * e_wv0[3];
                int idx = row * HID + j0 + tx;
                float cn = sigm(gf) * g_ec0[idx] + sigm(gi) * tanhf(gg);
                g_ec0[idx] = cn;
                g_eh0[p & 1][idx] = sigm(go) * tanhf(cn);
            }
        }
        if (p > 0) {
            float2 acc[2][4];
#pragma unroll
            for (int r = 0; r < 2; ++r)
#pragma unroll
                for (int c = 0; c < 4; ++c) acc[r][c] = make_float2(0.f, 0.f);
            gemm256<2>(W1f, hA,  eRow0, acc, ty, tx);
            gemm256<2>(W2f, h1r, eRow0, acc, ty, tx);
#pragma unroll
            for (int r = 0; r < 2; ++r) {
                int row = eRow0 + ty + 16 * r;
                float gi = acc[r][0].x + acc[r][0].y + e_bv1[0];
                float gf = acc[r][1].x + acc[r][1].y + e_bv1[1];
                float gg = acc[r][2].x + acc[r][2].y + e_bv1[2];
                float go = acc[r][3].x + acc[r][3].y + e_bv1[3];
                int idx = row * HID + j0 + tx;
                float cn = sigm(gf) * g_ec1[idx] + sigm(gi) * tanhf(gg);
                g_ec1[idx] = cn;
                g_eh1[(p + 1) & 1][idx] = sigm(go) * tanhf(cn);
            }
        }
        gsync();
    }

    // ============== decoder setup: fragment W into smem + state broadcast =====
    for (int i = tid; i < 12288; i += NTHR) {       // 192KB in 16B chunks
        int m = i / 4096, rest = i - m * 4096;
        int part = rest >> 11, c = rest & 2047;
        cpa16(smem + m * WREG + part * 32768 + c * 16,
              (const char*)&g_wfrag[m][part][jt][0] + c * 16);
    }
    cp_commit();
    float* b0s = (float*)(smem + CTRL);
    float* w0s = b0s + 64;
    float* b1s = w0s + 64;
    float* ows = b1s + 64;
    for (int i = tid; i < 64; i += NTHR) {
        int g = i >> 4, j = i & 15;
        int gr = g * HID + j0 + j;
        b0s[i] = db0[gr]; w0s[i] = dWih0[gr]; b1s[i] = db1[gr];
        if (i < 16) ows[i] = outW[j0 + i];
    }
    for (int i = blockIdx.x * NTHR + tid; i < SBAT * HID; i += GRID * NTHR) {
        int src = i & (BATCH * HID - 1);
        __nv_bfloat16 hh, hl;
        bsplit(__ldcg(&g_eh0[1][src]), hh, hl);
        g_h0b[1][0][i] = hh; g_h0b[1][1][i] = hl;
        bsplit(__ldcg(&g_eh1[1][src]), hh, hl);
        g_h1b[1][0][i] = hh; g_h1b[1][1][i] = hl;
        g_dc0[i] = __ldcg(&g_ec0[src]);
        g_dc1[i] = __ldcg(&g_ec1[src]);
    }
    cp_wait0();
    gsync();

    const float outbv = outb[0];
    const int q = lane & 3, r4 = lane >> 2;
    const int wrow = dRow0 + w * 64;

    // =========================== decoder (mma.sync) ===========================
    for (int t = 0; t < HOR; ++t) {
        const int rp = (t + 1) & 1, wp = t & 1;

        // ---- layer0: gates = h0_prev @ Whh0^T ----
        if (tid < 32) g_pred[wp][blockIdx.x * 32 + tid] = 0.f;
        {
            float acc[4][8][4];
#pragma unroll
            for (int mi = 0; mi < 4; ++mi)
#pragma unroll
                for (int n = 0; n < 8; ++n)
#pragma unroll
                    for (int d = 0; d < 4; ++d) acc[mi][n][d] = 0.f;
            mma_gemm256(acc, g_h0b[rp][0], g_h0b[rp][1], smem, wrow, lane);
#pragma unroll
            for (int mi = 0; mi < 4; ++mi)
#pragma unroll
                for (int rr = 0; rr < 2; ++rr) {
                    int row = wrow + mi * 16 + r4 + rr * 8;
                    float iv;
                    if (t == 0) iv = __ldcg(&dinit[row]);
                    else {
                        iv = __ldcg(&g_pred[rp][row]) + outbv;
                        if (jt == 0 && q == 0)
                            out[(size_t)(row & 255) * (NS * HOR)
                                + (row >> 8) * HOR + (t - 1)] = iv;
                    }
#pragma unroll
                    for (int jj = 0; jj < 4; ++jj) {
                        int j = 2 * q + (jj & 1) + (jj >> 1) * 8;
                        int hb = jj >> 1, dr = rr * 2 + (jj & 1);
                        float gi = acc[mi][hb][dr]     + b0s[j]      + iv * w0s[j];
                        float gf = acc[mi][2 + hb][dr] + b0s[16 + j] + iv * w0s[16 + j];
                        float gg = acc[mi][4 + hb][dr] + b0s[32 + j] + iv * w0s[32 + j];
                        float go = acc[mi][6 + hb][dr] + b0s[48 + j] + iv * w0s[48 + j];
                        int ci = row * HID + j0 + j;
                        float cn = sigm(gf) * g_dc0[ci] + sigm(gi) * tanhf(gg);
                        g_dc0[ci] = cn;
                        float h = sigm(go) * tanhf(cn);
                        __nv_bfloat16 hh, hl; bsplit(h, hh, hl);
                        g_h0b[wp][0][ci] = hh; g_h0b[wp][1][ci] = hl;
                    }
                }
        }
        gsync();

        // ---- layer1: gates = h0_cur @ Wih1^T + h1_prev @ Whh1^T (+ proj) ----
        {
            float acc[4][8][4];
#pragma unroll
            for (int mi = 0; mi < 4; ++mi)
#pragma unroll
                for (int n = 0; n < 8; ++n)
#pragma unroll
                    for (int d = 0; d < 4; ++d) acc[mi][n][d] = 0.f;
            mma_gemm256(acc, g_h0b[wp][0], g_h0b[wp][1], smem + WREG, wrow, lane);
            mma_gemm256(acc, g_h1b[rp][0], g_h1b[rp][1], smem + 2 * WREG, wrow, lane);
#pragma unroll
            for (int mi = 0; mi < 4; ++mi)
#pragma unroll
                for (int rr = 0; rr < 2; ++rr) {
                    int row = wrow + mi * 16 + r4 + rr * 8;
                    float psum = 0.f;
#pragma unroll
                    for (int jj = 0; jj < 4; ++jj) {
                        int j = 2 * q + (jj & 1) + (jj >> 1) * 8;
                        int hb = jj >> 1, dr = rr * 2 + (jj & 1);
                        float gi = acc[mi][hb][dr]     + b1s[j];
                        float gf = acc[mi][2 + hb][dr] + b1s[16 + j];
                        float gg = acc[mi][4 + hb][dr] + b1s[32 + j];
                        float go = acc[mi][6 + hb][dr] + b1s[48 + j];
                        int ci = row * HID + j0 + j;
                        float cn = sigm(gf) * g_dc1[ci] + sigm(gi) * tanhf(gg);
                        g_dc1[ci] = cn;
                        float h = sigm(go) * tanhf(cn);
                        __nv_bfloat16 hh, hl; bsplit(h, hh, hl);
                        g_h1b[wp][0][ci] = hh; g_h1b[wp][1][ci] = hl;
                        psum += h * ows[j];
                    }
                    psum += __shfl_xor_sync(0xffffffffu, psum, 1);
                    psum += __shfl_xor_sync(0xffffffffu, psum, 2);
                    if (q == 0) atomicAdd(&g_pred[wp][row], psum);
                }
        }
        gsync();
    }

    // ---- tail output ----
    if (tid < 32) {
        int row = blockIdx.x * 32 + tid;
        float v = __ldcg(&g_pred[(HOR - 1) & 1][row]) + outbv;
        out[(size_t)(row & 255) * (NS * HOR) + (row >> 8) * HOR + (HOR - 1)] = v;
    }
}

// ---------------------------------------------------------------------------
extern "C" void kernel_launch(void* const* d_in, const int* in_sizes, int n_in,
                              void* d_out, int out_size)
{
    (void)in_sizes; (void)n_in; (void)out_size;
    const float* x     = (const float*)d_in[0];
    const float* eWih0 = (const float*)d_in[1];
    const float* eWhh0 = (const float*)d_in[2];
    const float* eb0   = (const float*)d_in[3];
    const float* eWih1 = (const float*)d_in[4];
    const float* eWhh1 = (const float*)d_in[5];
    const float* eb1   = (const float*)d_in[6];
    const float* dWih0 = (const float*)d_in[7];
    const float* dWhh0 = (const float*)d_in[8];
    const float* db0   = (const float*)d_in[9];
    const float* dWih1 = (const float*)d_in[10];
    const float* dWhh1 = (const float*)d_in[11];
    const float* db1   = (const float*)d_in[12];
    const float* outW  = (const float*)d_in[13];
    const float* outb  = (const float*)d_in[14];
    const float* dinit = (const float*)d_in[15];
    float* out = (float*)d_out;

    cudaFuncSetAttribute(lstm_all, cudaFuncAttributeMaxDynamicSharedMemorySize,
                         SMEM_BYTES);
    lstm_all<<<GRID, NTHR, SMEM_BYTES>>>(x, eWih0, eWhh0, eb0, eWih1, eWhh1, eb1,
                                         dWih0, dWhh0, db0, dWih1, dWhh1, db1,
                                         outW, outb, dinit, out);
}

// round 11
// speedup vs baseline: 3.2985x; 1.2940x over previous
#include <cuda_runtime.h>
#include <cuda_bf16.h>

#define HID   256
#define BATCH 256
#define TLEN  512
#define NS    16
#define SBAT  4096
#define HOR   64
#define GRID  128
#define NTHR  256
#define WREG  65536
#define CTRL  196608
#define SMEM_BYTES (CTRL + 16640 + 1024)

// ---------------- device state ----------------------------------------------
__device__ float g_ec0[BATCH * HID];
__device__ float g_ec1[BATCH * HID];
__device__ unsigned g_eh0p[2][BATCH * HID];   // packed (bf16 hi | lo<<16)
__device__ unsigned g_eh1p[2][BATCH * HID];

__device__ float g_dc0[SBAT * HID];
__device__ float g_dc1[SBAT * HID];
__device__ float g_pred[2][SBAT];
__device__ unsigned g_h0p[2][SBAT * HID];
__device__ unsigned g_h1p[2][SBAT * HID];

// fragment-ordered bf16 weight images: [mat 0..5][part hi/lo][jt][16384 elems]
// mats: 0 dWhh0, 1 dWih1, 2 dWhh1, 3 eWhh0, 4 eWih1, 5 eWhh1
__device__ __nv_bfloat16 g_fr[6][2][16][16384];

__device__ unsigned g_cnt = 0;
__device__ volatile unsigned g_gen = 0;

__device__ __forceinline__ void gsync() {
    __syncthreads();
    if (threadIdx.x == 0) {
        __threadfence();
        unsigned old = g_gen;
        unsigned a = atomicAdd(&g_cnt, 1u);
        if (a == gridDim.x - 1) { g_cnt = 0; __threadfence(); g_gen = old + 1u; }
        else { while (g_gen == old) { } __threadfence(); }
    }
    __syncthreads();
}
__device__ __forceinline__ float sigm(float x) { return 1.0f / (1.0f + expf(-x)); }
__device__ __forceinline__ void bsplit(float v, __nv_bfloat16& h, __nv_bfloat16& l) {
    h = __float2bfloat16(v);
    l = __float2bfloat16(v - __bfloat162float(h));
}
__device__ __forceinline__ unsigned packh(float v) {
    __nv_bfloat16 hh, hl; bsplit(v, hh, hl);
    return (unsigned)__bfloat16_as_ushort(hh) |
           ((unsigned)__bfloat16_as_ushort(hl) << 16);
}
__device__ __forceinline__ void cpa16(void* dst, const void* src) {
    unsigned d = (unsigned)__cvta_generic_to_shared(dst);
    asm volatile("cp.async.cg.shared.global [%0], [%1], 16;" :: "r"(d), "l"(src));
}
__device__ __forceinline__ void cp_commit() { asm volatile("cp.async.commit_group;" ::: "memory"); }
__device__ __forceinline__ void cp_wait0()  { asm volatile("cp.async.wait_group 0;" ::: "memory"); }

__device__ __forceinline__ void hmma(float (&d)[4], const unsigned (&a)[4],
                                     unsigned b0, unsigned b1) {
    asm volatile(
        "mma.sync.aligned.m16n8k16.row.col.f32.bf16.bf16.f32 "
        "{%0,%1,%2,%3}, {%4,%5,%6,%7}, {%8,%9}, {%0,%1,%2,%3};"
        : "+f"(d[0]), "+f"(d[1]), "+f"(d[2]), "+f"(d[3])
        : "r"(a[0]), "r"(a[1]), "r"(a[2]), "r"(a[3]), "r"(b0), "r"(b1));
}

// Load A-fragments (hi+lo) from packed u32 [row*256+k] via LDG.64 + PRMT.
__device__ __forceinline__ void ldAp(unsigned (&ah)[4], unsigned (&al)[4],
                                     const unsigned* Ap, int row, int kk) {
    const uint2* pr  = (const uint2*)(Ap + (size_t)row * HID + kk);
    const uint2* pr8 = (const uint2*)(Ap + (size_t)(row + 8) * HID + kk);
    uint2 p0 = __ldcg(pr), p1 = __ldcg(pr + 4);
    uint2 p2 = __ldcg(pr8), p3 = __ldcg(pr8 + 4);
    ah[0] = __byte_perm(p0.x, p0.y, 0x5410); al[0] = __byte_perm(p0.x, p0.y, 0x7632);
    ah[1] = __byte_perm(p2.x, p2.y, 0x5410); al[1] = __byte_perm(p2.x, p2.y, 0x7632);
    ah[2] = __byte_perm(p1.x, p1.y, 0x5410); al[2] = __byte_perm(p1.x, p1.y, 0x7632);
    ah[3] = __byte_perm(p3.x, p3.y, 0x5410); al[3] = __byte_perm(p3.x, p3.y, 0x7632);
}

// Decoder GEMM: acc[4 m16][8 n8][4] += A(64 rows, K=256) @ Wfrag^T (3-product)
__device__ __forceinline__ void mma_gemm256p(float (&acc)[4][8][4],
    const unsigned* __restrict__ Ap, const char* __restrict__ wreg,
    int wrow, int lane)
{
    const int r4 = lane >> 2, q = lane & 3;
#pragma unroll 2
    for (int k16 = 0; k16 < 16; ++k16) {
        unsigned ah[4][4], al[4][4];
        int kk = k16 * 16 + q * 2;
#pragma unroll
        for (int mi = 0; mi < 4; ++mi)
            ldAp(ah[mi], al[mi], Ap, wrow + mi * 16 + r4, kk);
#pragma unroll
        for (int n8 = 0; n8 < 8; ++n8) {
            unsigned off = (unsigned)(((k16 * 8 + n8) * 32 + lane) * 8);
            uint2 bh = *(const uint2*)(wreg + off);
            uint2 bl = *(const uint2*)(wreg + 32768 + off);
#pragma unroll
            for (int mi = 0; mi < 4; ++mi) {
                hmma(acc[mi][n8], ah[mi], bh.x, bh.y);
                hmma(acc[mi][n8], ah[mi], bl.x, bl.y);
                hmma(acc[mi][n8], al[mi], bh.x, bh.y);
            }
        }
    }
}

// Encoder GEMM: acc[2 n8sub][4] += A(16 rows at row0, K=256) @ Wfrag^T, one gate
__device__ __forceinline__ void enc_gemm(float (&acc)[2][4],
    const unsigned* __restrict__ Ap, const char* __restrict__ wreg,
    int row0, int gate, int lane)
{
    const int r4 = lane >> 2, q = lane & 3;
#pragma unroll 2
    for (int k16 = 0; k16 < 16; ++k16) {
        unsigned ah[4], al[4];
        int kk = k16 * 16 + q * 2;
        ldAp(ah, al, Ap, row0 + r4, kk);
#pragma unroll
        for (int s = 0; s < 2; ++s) {
            unsigned off = (unsigned)(((k16 * 8 + gate * 2 + s) * 32 + lane) * 8);
            uint2 bh = *(const uint2*)(wreg + off);
            uint2 bl = *(const uint2*)(wreg + 32768 + off);
            hmma(acc[s], ah, bh.x, bh.y);
            hmma(acc[s], ah, bl.x, bl.y);
            hmma(acc[s], al, bh.x, bh.y);
        }
    }
}

// ---------------------------------------------------------------------------
__global__ void __launch_bounds__(NTHR, 1)
lstm_all(const float* __restrict__ x,
         const float* __restrict__ eWih0, const float* __restrict__ eWhh0,
         const float* __restrict__ eb0,
         const float* __restrict__ eWih1, const float* __restrict__ eWhh1,
         const float* __restrict__ eb1,
         const float* __restrict__ dWih0, const float* __restrict__ dWhh0,
         const float* __restrict__ db0,
         const float* __restrict__ dWih1, const float* __restrict__ dWhh1,
         const float* __restrict__ db1,
         const float* __restrict__ outW, const float* __restrict__ outb,
         const float* __restrict__ dinit,
         float* __restrict__ out)
{
    extern __shared__ char smem[];
    const int tid = threadIdx.x;
    const int w = tid >> 5, lane = tid & 31;
    const int q = lane & 3, r4 = lane >> 2;
    const int jt = blockIdx.x >> 3, j0 = jt * 16;
    const int grp = blockIdx.x & 7, eRow0 = grp * 32, dRow0 = grp * 512;

    float* gsm0 = (float*)(smem + CTRL);          // [32][65]
    float* gsm1 = gsm0 + 32 * 65;
    float* b0s = (float*)(smem + CTRL + 16640);   // 64
    float* w0s = b0s + 64;
    float* b1s = w0s + 64;
    float* ows = b1s + 64;

    // ---- init: build ALL fragment images + zero state ----
    {
        const float* Wsrc[6] = { dWhh0, dWih1, dWhh1, eWhh0, eWih1, eWhh1 };
        for (int idx = blockIdx.x * NTHR + tid; idx < 6 * 32 * 16384;
             idx += GRID * NTHR) {
            int e = idx & 16383;
            int rgn = idx >> 14;
            int ijt = rgn & 15, part = (rgn >> 4) & 1, m = rgn >> 5;
            int reg = e & 3, ln = (e >> 2) & 31, blk = e >> 7;
            int n8 = blk & 7, k16 = blk >> 3;
            int k = k16 * 16 + (ln & 3) * 2 + (reg & 1) + (reg >> 1) * 8;
            int nl = n8 * 8 + (ln >> 2);
            int gate = nl >> 4, j = nl & 15;
            float v = Wsrc[m][(size_t)(gate * HID + ijt * 16 + j) * HID + k];
            __nv_bfloat16 hh, hl; bsplit(v, hh, hl);
            g_fr[m][part][ijt][e] = part ? hl : hh;
        }
    }
    for (int i = blockIdx.x * NTHR + tid; i < BATCH * HID; i += GRID * NTHR) {
        g_eh0p[1][i] = 0u; g_ec0[i] = 0.f;
        g_eh1p[1][i] = 0u; g_ec1[i] = 0.f;
    }
    gsync();   // fragment images complete before any CTA stages them

    // ---- stage encoder W fragments into smem + encoder bias ----
    for (int i = tid; i < 12288; i += NTHR) {
        int m = i / 4096, rest = i - m * 4096;
        int part = rest >> 11, c = rest & 2047;
        cpa16(smem + m * WREG + part * 32768 + c * 16,
              (const char*)&g_fr[3 + m][part][jt][0] + c * 16);
    }
    cp_commit();
    for (int i = tid; i < 64; i += NTHR) {
        int g = i >> 4, j = i & 15;
        int gr = g * HID + j0 + j;
        b0s[i] = eb0[gr]; w0s[i] = eWih0[gr]; b1s[i] = eb1[gr];
    }
    cp_wait0();
    gsync();

    const int egate = w >> 1, emh = w & 1;        // encoder warp roles

    // =========================== encoder (mma.sync, skewed) ===================
    for (int p = 0; p <= TLEN; ++p) {
        const unsigned* A0 = g_eh0p[(p + 1) & 1];   // h0(p-1)
        const unsigned* A1 = g_eh1p[p & 1];         // h1(p-2)

        if (p < TLEN) {
            float acc[2][4];
#pragma unroll
            for (int s = 0; s < 2; ++s)
#pragma unroll
                for (int d = 0; d < 4; ++d) acc[s][d] = 0.f;
            enc_gemm(acc, A0, smem, eRow0 + emh * 16, egate, lane);
#pragma unroll
            for (int s = 0; s < 2; ++s)
#pragma unroll
                for (int d = 0; d < 4; ++d)
                    gsm0[(emh * 16 + r4 + (d >> 1) * 8) * 65
                         + egate * 16 + s * 8 + 2 * q + (d & 1)] = acc[s][d];
        }
        if (p > 0) {
            float acc[2][4];
#pragma unroll
            for (int s = 0; s < 2; ++s)
#pragma unroll
                for (int d = 0; d < 4; ++d) acc[s][d] = 0.f;
            enc_gemm(acc, A0, smem + WREG,     eRow0 + emh * 16, egate, lane);
            enc_gemm(acc, A1, smem + 2 * WREG, eRow0 + emh * 16, egate, lane);
#pragma unroll
            for (int s = 0; s < 2; ++s)
#pragma unroll
                for (int d = 0; d < 4; ++d)
                    gsm1[(emh * 16 + r4 + (d >> 1) * 8) * 65
                         + egate * 16 + s * 8 + 2 * q + (d & 1)] = acc[s][d];
        }
        __syncthreads();

        // cell updates (thread = 2 cells per layer)
        if (p < TLEN) {
#pragma unroll
            for (int u = 0; u < 2; ++u) {
                int cidx = tid + u * 256;
                int row = cidx >> 4, j = cidx & 15;
                const float* gr = gsm0 + row * 65;
                float xv = x[(size_t)(eRow0 + row) * TLEN + p];
                float gi = gr[j]      + b0s[j]      + xv * w0s[j];
                float gf = gr[16 + j] + b0s[16 + j] + xv * w0s[16 + j];
                float gg = gr[32 + j] + b0s[32 + j] + xv * w0s[32 + j];
                float go = gr[48 + j] + b0s[48 + j] + xv * w0s[48 + j];
                int ci = (eRow0 + row) * HID + j0 + j;
                float cn = sigm(gf) * g_ec0[ci] + sigm(gi) * tanhf(gg);
                g_ec0[ci] = cn;
                g_eh0p[p & 1][ci] = packh(sigm(go) * tanhf(cn));
            }
        }
        if (p > 0) {
#pragma unroll
            for (int u = 0; u < 2; ++u) {
                int cidx = tid + u * 256;
                int row = cidx >> 4, j = cidx & 15;
                const float* gr = gsm1 + row * 65;
                float gi = gr[j]      + b1s[j];
                float gf = gr[16 + j] + b1s[16 + j];
                float gg = gr[32 + j] + b1s[32 + j];
                float go = gr[48 + j] + b1s[48 + j];
                int ci = (eRow0 + row) * HID + j0 + j;
                float cn = sigm(gf) * g_ec1[ci] + sigm(gi) * tanhf(gg);
                g_ec1[ci] = cn;
                g_eh1p[(p + 1) & 1][ci] = packh(sigm(go) * tanhf(cn));
            }
        }
        gsync();
    }

    // ============== decoder setup: W frags + bias + state broadcast ===========
    for (int i = tid; i < 12288; i += NTHR) {
        int m = i / 4096, rest = i - m * 4096;
        int part = rest >> 11, c = rest & 2047;
        cpa16(smem + m * WREG + part * 32768 + c * 16,
              (const char*)&g_fr[m][part][jt][0] + c * 16);
    }
    cp_commit();
    for (int i = tid; i < 64; i += NTHR) {
        int g = i >> 4, j = i & 15;
        int gr = g * HID + j0 + j;
        b0s[i] = db0[gr]; w0s[i] = dWih0[gr]; b1s[i] = db1[gr];
        if (i < 16) ows[i] = outW[j0 + i];
    }
    for (int i = blockIdx.x * NTHR + tid; i < SBAT * HID; i += GRID * NTHR) {
        int src = i & (BATCH * HID - 1);
        g_h0p[1][i] = __ldcg(&g_eh0p[1][src]);
        g_h1p[1][i] = __ldcg(&g_eh1p[1][src]);
        g_dc0[i] = __ldcg(&g_ec0[src]);
        g_dc1[i] = __ldcg(&g_ec1[src]);
    }
    cp_wait0();
    gsync();

    const float outbv = outb[0];
    const int wrow = dRow0 + w * 64;

    // =========================== decoder (mma.sync) ===========================
    for (int t = 0; t < HOR; ++t) {
        const int rp = (t + 1) & 1, wp = t & 1;

        // ---- layer0 ----
        if (tid < 32) g_pred[wp][blockIdx.x * 32 + tid] = 0.f;
        {
            float acc[4][8][4];
#pragma unroll
            for (int mi = 0; mi < 4; ++mi)
#pragma unroll
                for (int n = 0; n < 8; ++n)
#pragma unroll
                    for (int d = 0; d < 4; ++d) acc[mi][n][d] = 0.f;
            mma_gemm256p(acc, g_h0p[rp], smem, wrow, lane);
#pragma unroll
            for (int mi = 0; mi < 4; ++mi)
#pragma unroll
                for (int rr = 0; rr < 2; ++rr) {
                    int row = wrow + mi * 16 + r4 + rr * 8;
                    float iv;
                    if (t == 0) iv = __ldcg(&dinit[row]);
                    else {
                        iv = __ldcg(&g_pred[rp][row]) + outbv;
                        if (jt == 0 && q == 0)
                            out[(size_t)(row & 255) * (NS * HOR)
                                + (row >> 8) * HOR + (t - 1)] = iv;
                    }
#pragma unroll
                    for (int jj = 0; jj < 4; ++jj) {
                        int j = 2 * q + (jj & 1) + (jj >> 1) * 8;
                        int hb = jj >> 1, dr = rr * 2 + (jj & 1);
                        float gi = acc[mi][hb][dr]     + b0s[j]      + iv * w0s[j];
                        float gf = acc[mi][2 + hb][dr] + b0s[16 + j] + iv * w0s[16 + j];
                        float gg = acc[mi][4 + hb][dr] + b0s[32 + j] + iv * w0s[32 + j];
                        float go = acc[mi][6 + hb][dr] + b0s[48 + j] + iv * w0s[48 + j];
                        int ci = row * HID + j0 + j;
                        float cn = sigm(gf) * g_dc0[ci] + sigm(gi) * tanhf(gg);
                        g_dc0[ci] = cn;
                        g_h0p[wp][ci] = packh(sigm(go) * tanhf(cn));
                    }
                }
        }
        gsync();

        // ---- layer1 (+ fused projection) ----
        {
            float acc[4][8][4];
#pragma unroll
            for (int mi = 0; mi < 4; ++mi)
#pragma unroll
                for (int n = 0; n < 8; ++n)
#pragma unroll
                    for (int d = 0; d < 4; ++d) acc[mi][n][d] = 0.f;
            mma_gemm256p(acc, g_h0p[wp], smem + WREG, wrow, lane);
            mma_gemm256p(acc, g_h1p[rp], smem + 2 * WREG, wrow, lane);
#pragma unroll
            for (int mi = 0; mi < 4; ++mi)
#pragma unroll
                for (int rr = 0; rr < 2; ++rr) {
                    int row = wrow + mi * 16 + r4 + rr * 8;
                    float psum = 0.f;
#pragma unroll
                    for (int jj = 0; jj < 4; ++jj) {
                        int j = 2 * q + (jj & 1) + (jj >> 1) * 8;
                        int hb = jj >> 1, dr = rr * 2 + (jj & 1);
                        float gi = acc[mi][hb][dr]     + b1s[j];
                        float gf = acc[mi][2 + hb][dr] + b1s[16 + j];
                        float gg = acc[mi][4 + hb][dr] + b1s[32 + j];
                        float go = acc[mi][6 + hb][dr] + b1s[48 + j];
                        int ci = row * HID + j0 + j;
                        float cn = sigm(gf) * g_dc1[ci] + sigm(gi) * tanhf(gg);
                        g_dc1[ci] = cn;
                        float h = sigm(go) * tanhf(cn);
                        g_h1p[wp][ci] = packh(h);
                        psum += h * ows[j];
                    }
                    psum += __shfl_xor_sync(0xffffffffu, psum, 1);
                    psum += __shfl_xor_sync(0xffffffffu, psum, 2);
                    if (q == 0) atomicAdd(&g_pred[wp][row], psum);
                }
        }
        gsync();
    }

    // ---- tail output ----
    if (tid < 32) {
        int row = blockIdx.x * 32 + tid;
        float v = __ldcg(&g_pred[(HOR - 1) & 1][row]) + outbv;
        out[(size_t)(row & 255) * (NS * HOR) + (row >> 8) * HOR + (HOR - 1)] = v;
    }
}

// ---------------------------------------------------------------------------
extern "C" void kernel_launch(void* const* d_in, const int* in_sizes, int n_in,
                              void* d_out, int out_size)
{
    (void)in_sizes; (void)n_in; (void)out_size;
    const float* x     = (const float*)d_in[0];
    const float* eWih0 = (const float*)d_in[1];
    const float* eWhh0 = (const float*)d_in[2];
    const float* eb0   = (const float*)d_in[3];
    const float* eWih1 = (const float*)d_in[4];
    const float* eWhh1 = (const float*)d_in[5];
    const float* eb1   = (const float*)d_in[6];
    const float* dWih0 = (const float*)d_in[7];
    const float* dWhh0 = (const float*)d_in[8];
    const float* db0   = (const float*)d_in[9];
    const float* dWih1 = (const float*)d_in[10];
    const float* dWhh1 = (const float*)d_in[11];
    const float* db1   = (const float*)d_in[12];
    const float* outW  = (const float*)d_in[13];
    const float* outb  = (const float*)d_in[14];
    const float* dinit = (const float*)d_in[15];
    float* out = (float*)d_out;

    cudaFuncSetAttribute(lstm_all, cudaFuncAttributeMaxDynamicSharedMemorySize,
                         SMEM_BYTES);
    lstm_all<<<GRID, NTHR, SMEM_BYTES>>>(x, eWih0, eWhh0, eb0, eWih1, eWhh1, eb1,
                                         dWih0, dWhh0, db0, dWih1, dWhh1, db1,
                                         outW, outb, dinit, out);
}